// round 14
// baseline (speedup 1.0000x reference)
#include <cuda_runtime.h>
#include <cuda_fp16.h>
#include <math.h>
#include <stdint.h>

#define H_DIM   1024
#define M_DIM   64
#define LS_DIM  2048
#define BATCH   4
#define SEQ     2048
#define NTOK    8192
#define PROJ_W  384
#define CHUNK   64
#define NCHUNK  32
#define CAT_NKT 66            // 64 ktiles of t (k=2048) + 2 ktiles of sr (k=64)

// -------- scratch (device globals; allocation-free rule) --------------------
__device__ __half g_xh[(size_t)NTOK * H_DIM];               // x, A-frag tiles [mt][kt][4096h]
__device__ __half g_projh[(size_t)NTOK * PROJ_W];           // natural row-major fp16
__device__ float  g_decay[NTOK];
__device__ __half g_cat[(size_t)64 * CAT_NKT * 4096];       // [t|sr] A-frag tiles
__device__ __half g_wp[(size_t)3 * 32 * 4096];              // B-frag tiles: [Wk|Wv|Wql|Wqr]
__device__ __half g_wug[(size_t)32 * 32 * 4096];            // B-frag tiles: [u64|g64] x32
__device__ __half g_wcat[(size_t)8 * CAT_NKT * 4096];       // B-frag tiles: [Wdown;Wrec]
__device__ float  g_cA[BATCH * NCHUNK];
__device__ float  g_cB[(size_t)BATCH * NCHUNK * 4096];
__device__ float  g_cS[(size_t)BATCH * NCHUNK * 4096];

// ---------------------------------------------------------------------------
__device__ __forceinline__ float silu_f(float x) { return x / (1.0f + expf(-x)); }

__device__ __forceinline__ void mma_h(float* c, uint4 a, uint32_t b0, uint32_t b1) {
    asm volatile(
        "mma.sync.aligned.m16n8k16.row.col.f32.f16.f16.f32 "
        "{%0,%1,%2,%3}, {%4,%5,%6,%7}, {%8,%9}, {%0,%1,%2,%3};"
        : "+f"(c[0]), "+f"(c[1]), "+f"(c[2]), "+f"(c[3])
        : "r"(a.x), "r"(a.y), "r"(a.z), "r"(a.w), "r"(b0), "r"(b1));
}

#define CP16(s, g)  asm volatile("cp.async.cg.shared.global [%0], [%1], 16;" :: "r"(s), "l"(g))
#define CPCOMMITG() asm volatile("cp.async.commit_group;" ::: "memory")
#define CPWAIT2()   asm volatile("cp.async.wait_group 2;" ::: "memory")

// A-frag-major half offset within a 128(m) x 32(k) tile (4096 halfs).
__device__ __forceinline__ int ah_off(int m, int k) {
    int wr = m >> 5, mi = (m >> 4) & 1, h = (m >> 3) & 1, g = m & 7;
    int ks = k >> 4, u = (k >> 3) & 1, tg = (k >> 1) & 3, e = k & 1;
    int word = ((wr * 4 + ks * 2 + mi) * 32 + g * 4 + tg) * 4 + h + 2 * u;
    return word * 2 + e;
}

// ---------------------------------------------------------------------------
// fp16 tensor-core GEMM. 256 threads = 8 warps (4x2), warp tile 32x64.
// BM=BN=128. Stage = 64 k (two 32-k ktiles) -> one barrier per 64 k.
// A: direct LDG.128, register double-buffered per 32-k half.
// B: 4-stage cp.async smem ring (16KB/stage, 64KB dynamic smem; 3-stage lookahead).
// WB 0: natural fp32 store (ldc). WB 1: fused swiglu -> g_cat (STG.128).
// WB 2: natural fp16 store (ldc in halfs).
// nkt (count of 32-k tiles) must be even.
// ---------------------------------------------------------------------------
template <int WB>
__global__ __launch_bounds__(256, 2) void gemm_h(
    const __half* __restrict__ A, const __half* __restrict__ B, void* __restrict__ Cv,
    int nkt, int ldc)
{
    extern __shared__ uint32_t sm[];    // 4 stages x 4096 words (16KB each)

    const int tid = threadIdx.x;
    const int w = tid >> 5, lane = tid & 31;
    const int wr = w & 3, wc = w >> 2;
    const int g = lane >> 2, tg = lane & 3;
    const int nst = nkt >> 1;

    const uint4* At = (const uint4*)(A + (size_t)blockIdx.y * nkt * 4096) + (wr * 4) * 32 + lane;
    const __half* Bbase = B + (size_t)blockIdx.x * nkt * 4096 + tid * 32;
    const uint32_t sb = (uint32_t)__cvta_generic_to_shared(sm);

    float acc[2][8][4];
#pragma unroll
    for (int mi = 0; mi < 2; ++mi)
#pragma unroll
        for (int j = 0; j < 8; ++j)
#pragma unroll
            for (int q = 0; q < 4; ++q) acc[mi][j][q] = 0.0f;

    // prologue: B stages 0..2 ; A frags ktile 0
#pragma unroll
    for (int p = 0; p < 3; ++p) {
        uint32_t sa = sb + p * 16384u + tid * 64u;
        const __half* gb = Bbase + (size_t)p * 8192;
        CP16(sa, gb); CP16(sa + 16, gb + 8); CP16(sa + 32, gb + 16); CP16(sa + 48, gb + 24);
        CPCOMMITG();
    }
    uint4 Ac[4], An[4];
#pragma unroll
    for (int q = 0; q < 4; ++q) Ac[q] = At[q * 32];

    for (int st = 0; st < nst; ++st) {
        const int s = st & 3;
        CPWAIT2();
        __syncthreads();
        if (st + 3 < nst) {
            const int s2 = (st + 3) & 3;
            uint32_t sa = sb + s2 * 16384u + tid * 64u;
            const __half* gb = Bbase + (size_t)(st + 3) * 8192;
            CP16(sa, gb); CP16(sa + 16, gb + 8); CP16(sa + 32, gb + 16); CP16(sa + 48, gb + 24);
        }
        CPCOMMITG();

#pragma unroll
        for (int half = 0; half < 2; ++half) {
            const int kt = st * 2 + half;
            if (kt + 1 < nkt) {
                const uint4* An_p = At + (size_t)(kt + 1) * 512;
#pragma unroll
                for (int q = 0; q < 4; ++q) An[q] = An_p[q * 32];
            }
            const uint32_t* bs = sm + s * 4096 + half * 2048;
#pragma unroll
            for (int ks = 0; ks < 2; ++ks) {
#pragma unroll
                for (int jp = 0; jp < 4; ++jp) {
                    uint4 bf = *(const uint4*)(bs + ((ks * 2 + wc) * 4 + jp) * 128 + lane * 4);
                    mma_h(acc[0][jp * 2],     Ac[ks * 2 + 0], bf.x, bf.y);
                    mma_h(acc[1][jp * 2],     Ac[ks * 2 + 1], bf.x, bf.y);
                    mma_h(acc[0][jp * 2 + 1], Ac[ks * 2 + 0], bf.z, bf.w);
                    mma_h(acc[1][jp * 2 + 1], Ac[ks * 2 + 1], bf.z, bf.w);
                }
            }
#pragma unroll
            for (int q = 0; q < 4; ++q) Ac[q] = An[q];
        }
    }

    if (WB == 0) {
        float* C = (float*)Cv;
#pragma unroll
        for (int mi = 0; mi < 2; ++mi) {
            const int row0 = blockIdx.y * 128 + wr * 32 + mi * 16 + g;
#pragma unroll
            for (int j = 0; j < 8; ++j) {
                const int col = blockIdx.x * 128 + wc * 64 + j * 8 + tg * 2;
                float* p0 = C + (size_t)row0 * ldc + col;
                float* p1 = p0 + 8 * ldc;
                p0[0] = acc[mi][j][0]; p0[1] = acc[mi][j][1];
                p1[0] = acc[mi][j][2]; p1[1] = acc[mi][j][3];
            }
        }
    } else if (WB == 2) {
        __half* C = (__half*)Cv;
#pragma unroll
        for (int mi = 0; mi < 2; ++mi) {
            const int row0 = blockIdx.y * 128 + wr * 32 + mi * 16 + g;
#pragma unroll
            for (int j = 0; j < 8; ++j) {
                const int col = blockIdx.x * 128 + wc * 64 + j * 8 + tg * 2;
                __half2 v0 = __floats2half2_rn(acc[mi][j][0], acc[mi][j][1]);
                __half2 v1 = __floats2half2_rn(acc[mi][j][2], acc[mi][j][3]);
                *(__half2*)(C + (size_t)row0 * ldc + col) = v0;
                *(__half2*)(C + (size_t)(row0 + 8) * ldc + col) = v1;
            }
        }
    } else {
        // fused swiglu: wc==1 warps hold gate; exchange silu(gate) via smem;
        // wc==0 warps store paired-j uint4 (coalesced STG.128)
        __syncthreads();
        float* smf = (float*)sm;               // [c][r], stride 129 (33KB <= 64KB)
        if (wc == 1) {
#pragma unroll
            for (int mi = 0; mi < 2; ++mi) {
                const int r = wr * 32 + mi * 16 + g;
#pragma unroll
                for (int j = 0; j < 8; ++j) {
                    const int c = j * 8 + tg * 2;
                    smf[c * 129 + r]           = silu_f(acc[mi][j][0]);
                    smf[(c + 1) * 129 + r]     = silu_f(acc[mi][j][1]);
                    smf[c * 129 + r + 8]       = silu_f(acc[mi][j][2]);
                    smf[(c + 1) * 129 + r + 8] = silu_f(acc[mi][j][3]);
                }
            }
        }
        __syncthreads();
        if (wc == 0) {
            __half* Ch = (__half*)Cv;
            const size_t mtb = (size_t)blockIdx.y * CAT_NKT * 4096;
#pragma unroll
            for (int mi = 0; mi < 2; ++mi) {
                const int r = wr * 32 + mi * 16 + g;
#pragma unroll
                for (int jq = 0; jq < 4; ++jq) {
                    const int j0 = jq * 2, j1 = jq * 2 + 1;
                    const int c = j0 * 8 + tg * 2;
                    float t0 = acc[mi][j0][0] * smf[c * 129 + r];
                    float t1 = acc[mi][j0][1] * smf[(c + 1) * 129 + r];
                    float t2 = acc[mi][j0][2] * smf[c * 129 + r + 8];
                    float t3 = acc[mi][j0][3] * smf[(c + 1) * 129 + r + 8];
                    float s0 = acc[mi][j1][0] * smf[(c + 8) * 129 + r];
                    float s1 = acc[mi][j1][1] * smf[(c + 9) * 129 + r];
                    float s2 = acc[mi][j1][2] * smf[(c + 8) * 129 + r + 8];
                    float s3 = acc[mi][j1][3] * smf[(c + 9) * 129 + r + 8];
                    const int colg = blockIdx.x * 64 + c;
                    const int kt = colg >> 5, kk = colg & 31;
                    __half* tb = Ch + mtb + (size_t)kt * 4096;
                    __half2 v0 = __floats2half2_rn(t0, t1);
                    __half2 v1 = __floats2half2_rn(t2, t3);
                    __half2 v2 = __floats2half2_rn(s0, s1);
                    __half2 v3 = __floats2half2_rn(s2, s3);
                    uint4 pk;
                    pk.x = *(uint32_t*)&v0; pk.y = *(uint32_t*)&v1;
                    pk.z = *(uint32_t*)&v2; pk.w = *(uint32_t*)&v3;
                    *(uint4*)(tb + ah_off(r, kk)) = pk;
                }
            }
        }
    }
}

// ---------------------------------------------------------------------------
// Packers (gather by output half index)
// ---------------------------------------------------------------------------
__global__ __launch_bounds__(256) void pack_xh(const float* __restrict__ x, __half* __restrict__ out)
{
    int o = blockIdx.x * 256 + threadIdx.x;       // NTOK * H halfs
    int tile = o >> 12, hi = o & 4095;
    int wd = hi >> 1, e = hi & 1;
    int idx = wd >> 7, lane = (wd >> 2) & 31, reg = wd & 3;
    int g = lane >> 2, tg = lane & 3;
    int wr = idx >> 2, ks = (idx >> 1) & 1, mi = idx & 1, h = reg & 1, u = reg >> 1;
    int m = wr * 32 + mi * 16 + h * 8 + g;
    int k = ks * 16 + u * 8 + tg * 2 + e;
    int mt = tile >> 5, kt = tile & 31;
    out[o] = __float2half_rn(x[(size_t)(mt * 128 + m) * H_DIM + kt * 32 + k]);
}

// B-frag packer. mode 0: wp (nkt=32), 1: wug (nkt=32), 2: wcat (nkt=66)
__global__ __launch_bounds__(256) void pack_bh(
    const float* __restrict__ S0, const float* __restrict__ S1,
    const float* __restrict__ S2, const float* __restrict__ S3,
    __half* __restrict__ out, int mode, int nkt)
{
    int o = blockIdx.x * 256 + threadIdx.x;
    int tile = o >> 12, hi = o & 4095;
    int nt = tile / nkt, kt = tile - nt * nkt;
    int wd = hi >> 1, e = hi & 1;
    int idx = wd >> 7, lane = (wd >> 2) & 31, wreg = wd & 3;
    int g = lane >> 2, tg = lane & 3;
    int jp = idx & 3, t2 = idx >> 2;
    int ks = t2 >> 1, wc = t2 & 1;
    int j = jp * 2 + (wreg >> 1), r = wreg & 1;
    int nl = wc * 64 + j * 8 + g;
    int kg = kt * 32 + ks * 16 + r * 8 + tg * 2 + e;

    float v;
    if (mode == 0) {
        int n = nt * 128 + nl;
        if (n < 128)      v = S0[(size_t)kg * 128 + n];
        else if (n < 256) v = S1[(size_t)kg * 128 + (n - 128)];
        else if (n < 320) v = S2[(size_t)kg * 64 + (n - 256)];
        else              v = S3[(size_t)kg * 64 + (n - 320)];
    } else if (mode == 1) {
        int col = nt * 64 + (nl & 63);
        v = (nl < 64) ? S0[(size_t)kg * LS_DIM + col] : S1[(size_t)kg * LS_DIM + col];
    } else {
        int n = nt * 128 + nl;
        v = (kg < 2048) ? S0[(size_t)kg * H_DIM + n] : S1[(size_t)(kg - 2048) * H_DIM + n];
    }
    out[o] = __float2half_rn(v);
}

// ---------------------------------------------------------------------------
__global__ __launch_bounds__(256) void decay_kernel(
    const float* __restrict__ x, const float* __restrict__ Wd, float* __restrict__ dec)
{
    const int token = blockIdx.x * 8 + (threadIdx.x >> 5);
    const int lane = threadIdx.x & 31;
    const float* xr = x + (size_t)token * H_DIM;
    float s = 0.0f;
#pragma unroll 8
    for (int j = lane; j < H_DIM; j += 32) s = fmaf(xr[j], Wd[j], s);
#pragma unroll
    for (int o = 16; o; o >>= 1) s += __shfl_xor_sync(0xffffffffu, s, o);
    if (lane == 0) dec[token] = 1.0f / (1.0f + expf(-s));
}

// ---------------------------------------------------------------------------
// Chunked scan — fp32 state, fp16 proj inputs (pass2 fully parallel)
// ---------------------------------------------------------------------------
__global__ __launch_bounds__(512) void scan_pass1(
    const __half* __restrict__ proj, const float* __restrict__ decay,
    float* __restrict__ cA, float* __restrict__ cB)
{
    const int b = blockIdx.y, c = blockIdx.x;
    const int tid = threadIdx.x;
    const int m = tid & 63, n0 = (tid >> 6) * 8;
    const size_t base = (size_t)b * SEQ + c * CHUNK;

    float st[8];
#pragma unroll
    for (int j = 0; j < 8; ++j) st[j] = 0.0f;
    float a = 1.0f;

    for (int s = 0; s < CHUNK; ++s) {
        const __half* row = proj + (base + s) * PROJ_W;
        float d = decay[base + s];
        float k0 = __half2float(row[m]), k1 = __half2float(row[64 + m]);
        uint4 u0 = *(const uint4*)(row + 128 + n0);
        uint4 u1 = *(const uint4*)(row + 192 + n0);
        const __half2* h0 = (const __half2*)&u0;
        const __half2* h1 = (const __half2*)&u1;
        float v0[8], v1[8];
#pragma unroll
        for (int q = 0; q < 4; ++q) {
            float2 f0 = __half22float2(h0[q]);
            float2 f1 = __half22float2(h1[q]);
            v0[q * 2] = f0.x; v0[q * 2 + 1] = f0.y;
            v1[q * 2] = f1.x; v1[q * 2 + 1] = f1.y;
        }
        a *= d;
        float omd = 1.0f - d;
#pragma unroll
        for (int j = 0; j < 8; ++j) {
            float wv = 0.5f * (k0 * v0[j] + k1 * v1[j]);
            st[j] = fmaf(d, st[j], omd * wv);
        }
    }
    float* o = cB + ((size_t)(b * NCHUNK + c) * 64 + m) * 64 + n0;
#pragma unroll
    for (int j = 0; j < 8; ++j) o[j] = st[j];
    if (tid == 0) cA[b * NCHUNK + c] = a;
}

// grid (NCHUNK, BATCH), 512 threads — parallel backward weighted sum
__global__ __launch_bounds__(512) void scan_pass2(
    const float* __restrict__ init_state, const float* __restrict__ cA,
    const float* __restrict__ cB, float* __restrict__ cS)
{
    const int c = blockIdx.x, b = blockIdx.y;
    const int i0 = threadIdx.x * 8;
    __shared__ float sa[NCHUNK];
    if ((int)threadIdx.x < c) sa[threadIdx.x] = cA[b * NCHUNK + threadIdx.x];
    __syncthreads();

    float st[8];
#pragma unroll
    for (int j = 0; j < 8; ++j) st[j] = 0.0f;
    float w = 1.0f;

    for (int j = c - 1; j >= 0; --j) {
        const float* Bp = cB + (size_t)(b * NCHUNK + j) * 4096 + i0;
        float4 b0 = *(const float4*)Bp;
        float4 b1 = *(const float4*)(Bp + 4);
        st[0] = fmaf(w, b0.x, st[0]); st[1] = fmaf(w, b0.y, st[1]);
        st[2] = fmaf(w, b0.z, st[2]); st[3] = fmaf(w, b0.w, st[3]);
        st[4] = fmaf(w, b1.x, st[4]); st[5] = fmaf(w, b1.y, st[5]);
        st[6] = fmaf(w, b1.z, st[6]); st[7] = fmaf(w, b1.w, st[7]);
        w *= sa[j];
    }
    const float* ip = init_state + i0;
    float* o = cS + (size_t)(b * NCHUNK + c) * 4096 + i0;
#pragma unroll
    for (int j = 0; j < 8; ++j) o[j] = fmaf(w, ip[j], st[j]);
}

__global__ __launch_bounds__(512) void scan_pass3(
    const __half* __restrict__ proj, const float* __restrict__ decay,
    const float* __restrict__ cS, __half* __restrict__ cat)
{
    const int b = blockIdx.z, c = blockIdx.y;
    const int n0 = blockIdx.x * 8;
    const int tid = threadIdx.x;
    const int nl = tid >> 6;
    const int m = tid & 63;
    const int n = n0 + nl;
    const int lane = tid & 31;
    const int half_ = (m >> 5);

    __shared__ float part[2][8][2];

    float st = cS[(size_t)(b * NCHUNK + c) * 4096 + m * 64 + n];
    const size_t base = (size_t)b * SEQ + c * CHUNK;

    const __half* row = proj + base * PROJ_W;
    float d = decay[base];
    float k0 = __half2float(row[m]), k1 = __half2float(row[64 + m]);
    float v0 = __half2float(row[128 + n]), v1 = __half2float(row[192 + n]);
    float qlm = __half2float(row[256 + m]), qrn = __half2float(row[320 + n]);

    for (int s = 0; s < CHUNK; ++s) {
        float nd = 0.f, nk0 = 0.f, nk1 = 0.f, nv0 = 0.f, nv1 = 0.f, nql = 0.f, nqr = 0.f;
        if (s + 1 < CHUNK) {
            const __half* nr = proj + (base + s + 1) * PROJ_W;
            nd = decay[base + s + 1];
            nk0 = __half2float(nr[m]);       nk1 = __half2float(nr[64 + m]);
            nv0 = __half2float(nr[128 + n]); nv1 = __half2float(nr[192 + n]);
            nql = __half2float(nr[256 + m]); nqr = __half2float(nr[320 + n]);
        }
        float wv = 0.5f * (k0 * v0 + k1 * v1);
        st = fmaf(d, st, (1.0f - d) * wv);

        float p = qlm * st;
#pragma unroll
        for (int o = 16; o; o >>= 1) p += __shfl_xor_sync(0xffffffffu, p, o);
        if (lane == 0) part[s & 1][nl][half_] = p;
        __syncthreads();
        if (m == 0) {
            float rd = (part[s & 1][nl][0] + part[s & 1][nl][1]) * qrn;
            int token = (int)(base + s);
            int mt = token >> 7, r = token & 127;
            int kt = 64 + (n >> 5), kk = n & 31;
            cat[((size_t)mt * CAT_NKT + kt) * 4096 + ah_off(r, kk)] = __float2half_rn(silu_f(rd));
        }
        d = nd; k0 = nk0; k1 = nk1; v0 = nv0; v1 = nv1; qlm = nql; qrn = nqr;
    }
}

// ---------------------------------------------------------------------------
extern "C" void kernel_launch(void* const* d_in, const int* in_sizes, int n_in,
                              void* d_out, int out_size)
{
    const float* x       = (const float*)d_in[0];
    const float* W_decay = (const float*)d_in[1];
    const float* W_key   = (const float*)d_in[2];
    const float* W_value = (const float*)d_in[3];
    const float* W_ql    = (const float*)d_in[4];
    const float* W_qr    = (const float*)d_in[5];
    const float* W_rec   = (const float*)d_in[6];
    const float* W_up    = (const float*)d_in[7];
    const float* W_gate  = (const float*)d_in[8];
    const float* W_down  = (const float*)d_in[9];
    const float* init_st = (const float*)d_in[10];
    float* out = (float*)d_out;

    void *p_xh, *p_proj, *p_dec, *p_cat, *p_wp, *p_wug, *p_wcat, *p_cA, *p_cB, *p_cS;
    cudaGetSymbolAddress(&p_xh,   g_xh);
    cudaGetSymbolAddress(&p_proj, g_projh);
    cudaGetSymbolAddress(&p_dec,  g_decay);
    cudaGetSymbolAddress(&p_cat,  g_cat);
    cudaGetSymbolAddress(&p_wp,   g_wp);
    cudaGetSymbolAddress(&p_wug,  g_wug);
    cudaGetSymbolAddress(&p_wcat, g_wcat);
    cudaGetSymbolAddress(&p_cA,   g_cA);
    cudaGetSymbolAddress(&p_cB,   g_cB);
    cudaGetSymbolAddress(&p_cS,   g_cS);
    __half* xh   = (__half*)p_xh;
    __half* proj = (__half*)p_proj;
    float*  dec  = (float*)p_dec;
    __half* cat  = (__half*)p_cat;
    __half* wp   = (__half*)p_wp;
    __half* wug  = (__half*)p_wug;
    __half* wcat = (__half*)p_wcat;
    float*  cA   = (float*)p_cA;
    float*  cB   = (float*)p_cB;
    float*  cS   = (float*)p_cS;

    // one-time stream/event/attr setup (no device memory involved)
    static cudaStream_t s_aux = nullptr;
    static cudaEvent_t evFork = nullptr, evXh = nullptr, evUg0 = nullptr, evUg1 = nullptr;
    if (!s_aux) {
        cudaStreamCreateWithFlags(&s_aux, cudaStreamNonBlocking);
        cudaEventCreateWithFlags(&evFork, cudaEventDisableTiming);
        cudaEventCreateWithFlags(&evXh, cudaEventDisableTiming);
        cudaEventCreateWithFlags(&evUg0, cudaEventDisableTiming);
        cudaEventCreateWithFlags(&evUg1, cudaEventDisableTiming);
        cudaFuncSetAttribute(gemm_h<0>, cudaFuncAttributeMaxDynamicSharedMemorySize, 65536);
        cudaFuncSetAttribute(gemm_h<1>, cudaFuncAttributeMaxDynamicSharedMemorySize, 65536);
        cudaFuncSetAttribute(gemm_h<2>, cudaFuncAttributeMaxDynamicSharedMemorySize, 65536);
    }

    const dim3 b256(256), b512(512);
    const size_t GSM = 65536;

    // fork immediately: aux runs the wug pack (independent of x)
    cudaEventRecord(evFork, 0);
    cudaStreamWaitEvent(s_aux, evFork, 0);
    pack_bh<<<(32 * 32 * 4096) / 256, b256, 0, s_aux>>>(W_up, W_gate, nullptr, nullptr, wug, 1, 32);

    // main stream: pack x
    pack_xh<<<(NTOK * H_DIM) / 256, b256>>>(x, xh);
    cudaEventRecord(evXh, 0);

    // aux: ug GEMM in two M-halves (fused swiglu -> cat kt 0..63)
    cudaStreamWaitEvent(s_aux, evXh, 0);
    gemm_h<1><<<dim3(32, 32), b256, GSM, s_aux>>>(xh, wug, cat, 32, 0);
    cudaEventRecord(evUg0, s_aux);
    gemm_h<1><<<dim3(32, 32), b256, GSM, s_aux>>>(xh + (size_t)32 * 32 * 4096, wug,
                                                  cat + (size_t)32 * CAT_NKT * 4096, 32, 0);
    cudaEventRecord(evUg1, s_aux);

    // main stream: proj chain + scan (all batches)
    pack_bh<<<(3 * 32 * 4096) / 256, b256>>>(W_key, W_value, W_ql, W_qr, wp, 0, 32);
    decay_kernel<<<NTOK / 8, b256>>>(x, W_decay, dec);
    gemm_h<2><<<dim3(3, 64), b256, GSM>>>(xh, wp, proj, 32, PROJ_W);
    scan_pass1<<<dim3(NCHUNK, BATCH), b512>>>(proj, dec, cA, cB);
    scan_pass2<<<dim3(NCHUNK, BATCH), b512>>>(init_st, cA, cB, cS);
    scan_pass3<<<dim3(8, NCHUNK, BATCH), b512>>>(proj, dec, cS, cat);
    pack_bh<<<(8 * CAT_NKT * 4096) / 256, b256>>>(W_down, W_rec, nullptr, nullptr, wcat, 2, CAT_NKT);

    // cat GEMM in two M-halves: first half starts as soon as ug half 0 + scan done
    cudaStreamWaitEvent(0, evUg0, 0);
    gemm_h<0><<<dim3(8, 32), b256, GSM>>>(cat, wcat, out, CAT_NKT, H_DIM);
    cudaStreamWaitEvent(0, evUg1, 0);
    gemm_h<0><<<dim3(8, 32), b256, GSM>>>(cat + (size_t)32 * CAT_NKT * 4096, wcat,
                                          out + (size_t)32 * 128 * H_DIM, CAT_NKT, H_DIM);
}

// round 15
// speedup vs baseline: 1.5031x; 1.5031x over previous
#include <cuda_runtime.h>
#include <cuda_fp16.h>
#include <math.h>
#include <stdint.h>

#define H_DIM   1024
#define M_DIM   64
#define LS_DIM  2048
#define BATCH   4
#define SEQ     2048
#define NTOK    8192
#define PROJ_W  384
#define CHUNK   64
#define NCHUNK  32
#define CAT_NKT 66            // 64 ktiles of t (k=2048) + 2 ktiles of sr (k=64)

// -------- scratch (device globals; allocation-free rule) --------------------
__device__ __half g_xh[(size_t)NTOK * H_DIM];               // x, A-frag tiles [mt][kt][4096h]
__device__ __half g_projh[(size_t)NTOK * PROJ_W];           // natural row-major fp16
__device__ float  g_decay[NTOK];
__device__ __half g_cat[(size_t)64 * CAT_NKT * 4096];       // [t|sr] A-frag tiles
__device__ __half g_wp[(size_t)3 * 32 * 4096];              // B-frag tiles: [Wk|Wv|Wql|Wqr]
__device__ __half g_wug[(size_t)32 * 32 * 4096];            // B-frag tiles: [u64|g64] x32
__device__ __half g_wcat[(size_t)8 * CAT_NKT * 4096];       // B-frag tiles: [Wdown;Wrec]
__device__ float  g_cA[BATCH * NCHUNK];
__device__ float  g_cB[(size_t)BATCH * NCHUNK * 4096];
__device__ float  g_cS[(size_t)BATCH * NCHUNK * 4096];

// ---------------------------------------------------------------------------
__device__ __forceinline__ float silu_f(float x) { return x / (1.0f + expf(-x)); }

__device__ __forceinline__ void mma_h(float* c, uint4 a, uint32_t b0, uint32_t b1) {
    asm volatile(
        "mma.sync.aligned.m16n8k16.row.col.f32.f16.f16.f32 "
        "{%0,%1,%2,%3}, {%4,%5,%6,%7}, {%8,%9}, {%0,%1,%2,%3};"
        : "+f"(c[0]), "+f"(c[1]), "+f"(c[2]), "+f"(c[3])
        : "r"(a.x), "r"(a.y), "r"(a.z), "r"(a.w), "r"(b0), "r"(b1));
}

#define CP16(s, g)  asm volatile("cp.async.cg.shared.global [%0], [%1], 16;" :: "r"(s), "l"(g))
#define CPCOMMITG() asm volatile("cp.async.commit_group;" ::: "memory")
#define CPWAIT1()   asm volatile("cp.async.wait_group 1;" ::: "memory")

// A-frag-major half offset within a 128(m) x 32(k) tile (4096 halfs).
__device__ __forceinline__ int ah_off(int m, int k) {
    int wr = m >> 5, mi = (m >> 4) & 1, h = (m >> 3) & 1, g = m & 7;
    int ks = k >> 4, u = (k >> 3) & 1, tg = (k >> 1) & 3, e = k & 1;
    int word = ((wr * 4 + ks * 2 + mi) * 32 + g * 4 + tg) * 4 + h + 2 * u;
    return word * 2 + e;
}

// ---------------------------------------------------------------------------
// fp16 tensor-core GEMM (round-13 proven config). 256 threads = 8 warps (4x2),
// warp tile 32x64, BM=BN=128. Stage = 64 k -> one barrier per 64 k.
// A: direct LDG.128, register double-buffered per 32-k half.
// B: 3-stage cp.async STATIC smem ring (16KB/stage, 48KB).
// WB 0: natural fp32 store (ldc). WB 1: fused swiglu -> g_cat (STG.128).
// WB 2: natural fp16 store (ldc in halfs).
// nkt must be even.
// ---------------------------------------------------------------------------
template <int WB>
__global__ __launch_bounds__(256, 2) void gemm_h(
    const __half* __restrict__ A, const __half* __restrict__ B, void* __restrict__ Cv,
    int nkt, int ldc)
{
    __shared__ uint32_t sm[12288];    // 3 stages x 4096 words (16KB) ; swiglu reuse

    const int tid = threadIdx.x;
    const int w = tid >> 5, lane = tid & 31;
    const int wr = w & 3, wc = w >> 2;
    const int g = lane >> 2, tg = lane & 3;
    const int nst = nkt >> 1;

    const uint4* At = (const uint4*)(A + (size_t)blockIdx.y * nkt * 4096) + (wr * 4) * 32 + lane;
    const __half* Bbase = B + (size_t)blockIdx.x * nkt * 4096 + tid * 32;
    const uint32_t sb = (uint32_t)__cvta_generic_to_shared(sm);

    float acc[2][8][4];
#pragma unroll
    for (int mi = 0; mi < 2; ++mi)
#pragma unroll
        for (int j = 0; j < 8; ++j)
#pragma unroll
            for (int q = 0; q < 4; ++q) acc[mi][j][q] = 0.0f;

    // prologue: B stages 0,1 ; A frags ktile 0
#pragma unroll
    for (int p = 0; p < 2; ++p) {
        uint32_t sa = sb + p * 16384u + tid * 64u;
        const __half* gb = Bbase + (size_t)p * 8192;
        CP16(sa, gb); CP16(sa + 16, gb + 8); CP16(sa + 32, gb + 16); CP16(sa + 48, gb + 24);
        CPCOMMITG();
    }
    uint4 Ac[4], An[4];
#pragma unroll
    for (int q = 0; q < 4; ++q) Ac[q] = At[q * 32];

    for (int st = 0; st < nst; ++st) {
        const int s = st - (st / 3) * 3;
        CPWAIT1();
        __syncthreads();
        if (st + 2 < nst) {
            const int s2 = (st + 2) - ((st + 2) / 3) * 3;
            uint32_t sa = sb + s2 * 16384u + tid * 64u;
            const __half* gb = Bbase + (size_t)(st + 2) * 8192;
            CP16(sa, gb); CP16(sa + 16, gb + 8); CP16(sa + 32, gb + 16); CP16(sa + 48, gb + 24);
        }
        CPCOMMITG();

#pragma unroll
        for (int half = 0; half < 2; ++half) {
            const int kt = st * 2 + half;
            if (kt + 1 < nkt) {
                const uint4* An_p = At + (size_t)(kt + 1) * 512;
#pragma unroll
                for (int q = 0; q < 4; ++q) An[q] = An_p[q * 32];
            }
            const uint32_t* bs = sm + s * 4096 + half * 2048;
#pragma unroll
            for (int ks = 0; ks < 2; ++ks) {
#pragma unroll
                for (int jp = 0; jp < 4; ++jp) {
                    uint4 bf = *(const uint4*)(bs + ((ks * 2 + wc) * 4 + jp) * 128 + lane * 4);
                    mma_h(acc[0][jp * 2],     Ac[ks * 2 + 0], bf.x, bf.y);
                    mma_h(acc[1][jp * 2],     Ac[ks * 2 + 1], bf.x, bf.y);
                    mma_h(acc[0][jp * 2 + 1], Ac[ks * 2 + 0], bf.z, bf.w);
                    mma_h(acc[1][jp * 2 + 1], Ac[ks * 2 + 1], bf.z, bf.w);
                }
            }
#pragma unroll
            for (int q = 0; q < 4; ++q) Ac[q] = An[q];
        }
    }

    if (WB == 0) {
        float* C = (float*)Cv;
#pragma unroll
        for (int mi = 0; mi < 2; ++mi) {
            const int row0 = blockIdx.y * 128 + wr * 32 + mi * 16 + g;
#pragma unroll
            for (int j = 0; j < 8; ++j) {
                const int col = blockIdx.x * 128 + wc * 64 + j * 8 + tg * 2;
                float* p0 = C + (size_t)row0 * ldc + col;
                float* p1 = p0 + 8 * ldc;
                p0[0] = acc[mi][j][0]; p0[1] = acc[mi][j][1];
                p1[0] = acc[mi][j][2]; p1[1] = acc[mi][j][3];
            }
        }
    } else if (WB == 2) {
        __half* C = (__half*)Cv;
#pragma unroll
        for (int mi = 0; mi < 2; ++mi) {
            const int row0 = blockIdx.y * 128 + wr * 32 + mi * 16 + g;
#pragma unroll
            for (int j = 0; j < 8; ++j) {
                const int col = blockIdx.x * 128 + wc * 64 + j * 8 + tg * 2;
                __half2 v0 = __floats2half2_rn(acc[mi][j][0], acc[mi][j][1]);
                __half2 v1 = __floats2half2_rn(acc[mi][j][2], acc[mi][j][3]);
                *(__half2*)(C + (size_t)row0 * ldc + col) = v0;
                *(__half2*)(C + (size_t)(row0 + 8) * ldc + col) = v1;
            }
        }
    } else {
        // fused swiglu: wc==1 warps hold gate; exchange silu(gate) via smem;
        // wc==0 warps store paired-j uint4 (coalesced STG.128)
        __syncthreads();
        float* smf = (float*)sm;               // [c][r], stride 129 (8256 <= 12288)
        if (wc == 1) {
#pragma unroll
            for (int mi = 0; mi < 2; ++mi) {
                const int r = wr * 32 + mi * 16 + g;
#pragma unroll
                for (int j = 0; j < 8; ++j) {
                    const int c = j * 8 + tg * 2;
                    smf[c * 129 + r]           = silu_f(acc[mi][j][0]);
                    smf[(c + 1) * 129 + r]     = silu_f(acc[mi][j][1]);
                    smf[c * 129 + r + 8]       = silu_f(acc[mi][j][2]);
                    smf[(c + 1) * 129 + r + 8] = silu_f(acc[mi][j][3]);
                }
            }
        }
        __syncthreads();
        if (wc == 0) {
            __half* Ch = (__half*)Cv;
            const size_t mtb = (size_t)blockIdx.y * CAT_NKT * 4096;
#pragma unroll
            for (int mi = 0; mi < 2; ++mi) {
                const int r = wr * 32 + mi * 16 + g;
#pragma unroll
                for (int jq = 0; jq < 4; ++jq) {
                    const int j0 = jq * 2, j1 = jq * 2 + 1;
                    const int c = j0 * 8 + tg * 2;
                    float t0 = acc[mi][j0][0] * smf[c * 129 + r];
                    float t1 = acc[mi][j0][1] * smf[(c + 1) * 129 + r];
                    float t2 = acc[mi][j0][2] * smf[c * 129 + r + 8];
                    float t3 = acc[mi][j0][3] * smf[(c + 1) * 129 + r + 8];
                    float s0 = acc[mi][j1][0] * smf[(c + 8) * 129 + r];
                    float s1 = acc[mi][j1][1] * smf[(c + 9) * 129 + r];
                    float s2 = acc[mi][j1][2] * smf[(c + 8) * 129 + r + 8];
                    float s3 = acc[mi][j1][3] * smf[(c + 9) * 129 + r + 8];
                    const int colg = blockIdx.x * 64 + c;
                    const int kt = colg >> 5, kk = colg & 31;
                    __half* tb = Ch + mtb + (size_t)kt * 4096;
                    __half2 v0 = __floats2half2_rn(t0, t1);
                    __half2 v1 = __floats2half2_rn(t2, t3);
                    __half2 v2 = __floats2half2_rn(s0, s1);
                    __half2 v3 = __floats2half2_rn(s2, s3);
                    uint4 pk;
                    pk.x = *(uint32_t*)&v0; pk.y = *(uint32_t*)&v1;
                    pk.z = *(uint32_t*)&v2; pk.w = *(uint32_t*)&v3;
                    *(uint4*)(tb + ah_off(r, kk)) = pk;
                }
            }
        }
    }
}

// ---------------------------------------------------------------------------
// Packers (gather by output half index)
// ---------------------------------------------------------------------------
__global__ __launch_bounds__(256) void pack_xh(const float* __restrict__ x, __half* __restrict__ out)
{
    int o = blockIdx.x * 256 + threadIdx.x;       // NTOK * H halfs
    int tile = o >> 12, hi = o & 4095;
    int wd = hi >> 1, e = hi & 1;
    int idx = wd >> 7, lane = (wd >> 2) & 31, reg = wd & 3;
    int g = lane >> 2, tg = lane & 3;
    int wr = idx >> 2, ks = (idx >> 1) & 1, mi = idx & 1, h = reg & 1, u = reg >> 1;
    int m = wr * 32 + mi * 16 + h * 8 + g;
    int k = ks * 16 + u * 8 + tg * 2 + e;
    int mt = tile >> 5, kt = tile & 31;
    out[o] = __float2half_rn(x[(size_t)(mt * 128 + m) * H_DIM + kt * 32 + k]);
}

// B-frag packer. mode 0: wp (nkt=32), 1: wug (nkt=32), 2: wcat (nkt=66)
__global__ __launch_bounds__(256) void pack_bh(
    const float* __restrict__ S0, const float* __restrict__ S1,
    const float* __restrict__ S2, const float* __restrict__ S3,
    __half* __restrict__ out, int mode, int nkt)
{
    int o = blockIdx.x * 256 + threadIdx.x;
    int tile = o >> 12, hi = o & 4095;
    int nt = tile / nkt, kt = tile - nt * nkt;
    int wd = hi >> 1, e = hi & 1;
    int idx = wd >> 7, lane = (wd >> 2) & 31, wreg = wd & 3;
    int g = lane >> 2, tg = lane & 3;
    int jp = idx & 3, t2 = idx >> 2;
    int ks = t2 >> 1, wc = t2 & 1;
    int j = jp * 2 + (wreg >> 1), r = wreg & 1;
    int nl = wc * 64 + j * 8 + g;
    int kg = kt * 32 + ks * 16 + r * 8 + tg * 2 + e;

    float v;
    if (mode == 0) {
        int n = nt * 128 + nl;
        if (n < 128)      v = S0[(size_t)kg * 128 + n];
        else if (n < 256) v = S1[(size_t)kg * 128 + (n - 128)];
        else if (n < 320) v = S2[(size_t)kg * 64 + (n - 256)];
        else              v = S3[(size_t)kg * 64 + (n - 320)];
    } else if (mode == 1) {
        int col = nt * 64 + (nl & 63);
        v = (nl < 64) ? S0[(size_t)kg * LS_DIM + col] : S1[(size_t)kg * LS_DIM + col];
    } else {
        int n = nt * 128 + nl;
        v = (kg < 2048) ? S0[(size_t)kg * H_DIM + n] : S1[(size_t)(kg - 2048) * H_DIM + n];
    }
    out[o] = __float2half_rn(v);
}

// ---------------------------------------------------------------------------
__global__ __launch_bounds__(256) void decay_kernel(
    const float* __restrict__ x, const float* __restrict__ Wd, float* __restrict__ dec)
{
    const int token = blockIdx.x * 8 + (threadIdx.x >> 5);
    const int lane = threadIdx.x & 31;
    const float* xr = x + (size_t)token * H_DIM;
    float s = 0.0f;
#pragma unroll 8
    for (int j = lane; j < H_DIM; j += 32) s = fmaf(xr[j], Wd[j], s);
#pragma unroll
    for (int o = 16; o; o >>= 1) s += __shfl_xor_sync(0xffffffffu, s, o);
    if (lane == 0) dec[token] = 1.0f / (1.0f + expf(-s));
}

// ---------------------------------------------------------------------------
// Chunked scan — fp32 state, fp16 proj inputs (pass2 fully parallel)
// ---------------------------------------------------------------------------
__global__ __launch_bounds__(512) void scan_pass1(
    const __half* __restrict__ proj, const float* __restrict__ decay,
    float* __restrict__ cA, float* __restrict__ cB)
{
    const int b = blockIdx.y, c = blockIdx.x;
    const int tid = threadIdx.x;
    const int m = tid & 63, n0 = (tid >> 6) * 8;
    const size_t base = (size_t)b * SEQ + c * CHUNK;

    float st[8];
#pragma unroll
    for (int j = 0; j < 8; ++j) st[j] = 0.0f;
    float a = 1.0f;

    for (int s = 0; s < CHUNK; ++s) {
        const __half* row = proj + (base + s) * PROJ_W;
        float d = decay[base + s];
        float k0 = __half2float(row[m]), k1 = __half2float(row[64 + m]);
        uint4 u0 = *(const uint4*)(row + 128 + n0);
        uint4 u1 = *(const uint4*)(row + 192 + n0);
        const __half2* h0 = (const __half2*)&u0;
        const __half2* h1 = (const __half2*)&u1;
        float v0[8], v1[8];
#pragma unroll
        for (int q = 0; q < 4; ++q) {
            float2 f0 = __half22float2(h0[q]);
            float2 f1 = __half22float2(h1[q]);
            v0[q * 2] = f0.x; v0[q * 2 + 1] = f0.y;
            v1[q * 2] = f1.x; v1[q * 2 + 1] = f1.y;
        }
        a *= d;
        float omd = 1.0f - d;
#pragma unroll
        for (int j = 0; j < 8; ++j) {
            float wv = 0.5f * (k0 * v0[j] + k1 * v1[j]);
            st[j] = fmaf(d, st[j], omd * wv);
        }
    }
    float* o = cB + ((size_t)(b * NCHUNK + c) * 64 + m) * 64 + n0;
#pragma unroll
    for (int j = 0; j < 8; ++j) o[j] = st[j];
    if (tid == 0) cA[b * NCHUNK + c] = a;
}

// grid (NCHUNK, BATCH), 512 threads — parallel backward weighted sum
__global__ __launch_bounds__(512) void scan_pass2(
    const float* __restrict__ init_state, const float* __restrict__ cA,
    const float* __restrict__ cB, float* __restrict__ cS)
{
    const int c = blockIdx.x, b = blockIdx.y;
    const int i0 = threadIdx.x * 8;
    __shared__ float sa[NCHUNK];
    if ((int)threadIdx.x < c) sa[threadIdx.x] = cA[b * NCHUNK + threadIdx.x];
    __syncthreads();

    float st[8];
#pragma unroll
    for (int j = 0; j < 8; ++j) st[j] = 0.0f;
    float w = 1.0f;

    for (int j = c - 1; j >= 0; --j) {
        const float* Bp = cB + (size_t)(b * NCHUNK + j) * 4096 + i0;
        float4 b0 = *(const float4*)Bp;
        float4 b1 = *(const float4*)(Bp + 4);
        st[0] = fmaf(w, b0.x, st[0]); st[1] = fmaf(w, b0.y, st[1]);
        st[2] = fmaf(w, b0.z, st[2]); st[3] = fmaf(w, b0.w, st[3]);
        st[4] = fmaf(w, b1.x, st[4]); st[5] = fmaf(w, b1.y, st[5]);
        st[6] = fmaf(w, b1.z, st[6]); st[7] = fmaf(w, b1.w, st[7]);
        w *= sa[j];
    }
    const float* ip = init_state + i0;
    float* o = cS + (size_t)(b * NCHUNK + c) * 4096 + i0;
#pragma unroll
    for (int j = 0; j < 8; ++j) o[j] = fmaf(w, ip[j], st[j]);
}

__global__ __launch_bounds__(512) void scan_pass3(
    const __half* __restrict__ proj, const float* __restrict__ decay,
    const float* __restrict__ cS, __half* __restrict__ cat)
{
    const int b = blockIdx.z, c = blockIdx.y;
    const int n0 = blockIdx.x * 8;
    const int tid = threadIdx.x;
    const int nl = tid >> 6;
    const int m = tid & 63;
    const int n = n0 + nl;
    const int lane = tid & 31;
    const int half_ = (m >> 5);

    __shared__ float part[2][8][2];

    float st = cS[(size_t)(b * NCHUNK + c) * 4096 + m * 64 + n];
    const size_t base = (size_t)b * SEQ + c * CHUNK;

    const __half* row = proj + base * PROJ_W;
    float d = decay[base];
    float k0 = __half2float(row[m]), k1 = __half2float(row[64 + m]);
    float v0 = __half2float(row[128 + n]), v1 = __half2float(row[192 + n]);
    float qlm = __half2float(row[256 + m]), qrn = __half2float(row[320 + n]);

    for (int s = 0; s < CHUNK; ++s) {
        float nd = 0.f, nk0 = 0.f, nk1 = 0.f, nv0 = 0.f, nv1 = 0.f, nql = 0.f, nqr = 0.f;
        if (s + 1 < CHUNK) {
            const __half* nr = proj + (base + s + 1) * PROJ_W;
            nd = decay[base + s + 1];
            nk0 = __half2float(nr[m]);       nk1 = __half2float(nr[64 + m]);
            nv0 = __half2float(nr[128 + n]); nv1 = __half2float(nr[192 + n]);
            nql = __half2float(nr[256 + m]); nqr = __half2float(nr[320 + n]);
        }
        float wv = 0.5f * (k0 * v0 + k1 * v1);
        st = fmaf(d, st, (1.0f - d) * wv);

        float p = qlm * st;
#pragma unroll
        for (int o = 16; o; o >>= 1) p += __shfl_xor_sync(0xffffffffu, p, o);
        if (lane == 0) part[s & 1][nl][half_] = p;
        __syncthreads();
        if (m == 0) {
            float rd = (part[s & 1][nl][0] + part[s & 1][nl][1]) * qrn;
            int token = (int)(base + s);
            int mt = token >> 7, r = token & 127;
            int kt = 64 + (n >> 5), kk = n & 31;
            cat[((size_t)mt * CAT_NKT + kt) * 4096 + ah_off(r, kk)] = __float2half_rn(silu_f(rd));
        }
        d = nd; k0 = nk0; k1 = nk1; v0 = nv0; v1 = nv1; qlm = nql; qrn = nqr;
    }
}

// ---------------------------------------------------------------------------
extern "C" void kernel_launch(void* const* d_in, const int* in_sizes, int n_in,
                              void* d_out, int out_size)
{
    const float* x       = (const float*)d_in[0];
    const float* W_decay = (const float*)d_in[1];
    const float* W_key   = (const float*)d_in[2];
    const float* W_value = (const float*)d_in[3];
    const float* W_ql    = (const float*)d_in[4];
    const float* W_qr    = (const float*)d_in[5];
    const float* W_rec   = (const float*)d_in[6];
    const float* W_up    = (const float*)d_in[7];
    const float* W_gate  = (const float*)d_in[8];
    const float* W_down  = (const float*)d_in[9];
    const float* init_st = (const float*)d_in[10];
    float* out = (float*)d_out;

    void *p_xh, *p_proj, *p_dec, *p_cat, *p_wp, *p_wug, *p_wcat, *p_cA, *p_cB, *p_cS;
    cudaGetSymbolAddress(&p_xh,   g_xh);
    cudaGetSymbolAddress(&p_proj, g_projh);
    cudaGetSymbolAddress(&p_dec,  g_decay);
    cudaGetSymbolAddress(&p_cat,  g_cat);
    cudaGetSymbolAddress(&p_wp,   g_wp);
    cudaGetSymbolAddress(&p_wug,  g_wug);
    cudaGetSymbolAddress(&p_wcat, g_wcat);
    cudaGetSymbolAddress(&p_cA,   g_cA);
    cudaGetSymbolAddress(&p_cB,   g_cB);
    cudaGetSymbolAddress(&p_cS,   g_cS);
    __half* xh   = (__half*)p_xh;
    __half* proj = (__half*)p_proj;
    float*  dec  = (float*)p_dec;
    __half* cat  = (__half*)p_cat;
    __half* wp   = (__half*)p_wp;
    __half* wug  = (__half*)p_wug;
    __half* wcat = (__half*)p_wcat;
    float*  cA   = (float*)p_cA;
    float*  cB   = (float*)p_cB;
    float*  cS   = (float*)p_cS;

    // one-time stream/event setup (no device memory involved)
    static cudaStream_t s_aux = nullptr;
    static cudaEvent_t evFork = nullptr, evXh = nullptr, evUg0 = nullptr, evUg1 = nullptr;
    if (!s_aux) {
        cudaStreamCreateWithFlags(&s_aux, cudaStreamNonBlocking);
        cudaEventCreateWithFlags(&evFork, cudaEventDisableTiming);
        cudaEventCreateWithFlags(&evXh, cudaEventDisableTiming);
        cudaEventCreateWithFlags(&evUg0, cudaEventDisableTiming);
        cudaEventCreateWithFlags(&evUg1, cudaEventDisableTiming);
    }

    const dim3 b256(256), b512(512);

    // fork immediately: aux runs the wug pack (independent of x)
    cudaEventRecord(evFork, 0);
    cudaStreamWaitEvent(s_aux, evFork, 0);
    pack_bh<<<(32 * 32 * 4096) / 256, b256, 0, s_aux>>>(W_up, W_gate, nullptr, nullptr, wug, 1, 32);

    // main stream: pack x
    pack_xh<<<(NTOK * H_DIM) / 256, b256>>>(x, xh);
    cudaEventRecord(evXh, 0);

    // aux: ug GEMM in two M-halves (fused swiglu -> cat kt 0..63)
    cudaStreamWaitEvent(s_aux, evXh, 0);
    gemm_h<1><<<dim3(32, 32), b256, 0, s_aux>>>(xh, wug, cat, 32, 0);
    cudaEventRecord(evUg0, s_aux);
    gemm_h<1><<<dim3(32, 32), b256, 0, s_aux>>>(xh + (size_t)32 * 32 * 4096, wug,
                                                cat + (size_t)32 * CAT_NKT * 4096, 32, 0);
    cudaEventRecord(evUg1, s_aux);

    // main stream: proj chain + scan (all batches)
    pack_bh<<<(3 * 32 * 4096) / 256, b256>>>(W_key, W_value, W_ql, W_qr, wp, 0, 32);
    decay_kernel<<<NTOK / 8, b256>>>(x, W_decay, dec);
    gemm_h<2><<<dim3(3, 64), b256>>>(xh, wp, proj, 32, PROJ_W);
    scan_pass1<<<dim3(NCHUNK, BATCH), b512>>>(proj, dec, cA, cB);
    scan_pass2<<<dim3(NCHUNK, BATCH), b512>>>(init_st, cA, cB, cS);
    scan_pass3<<<dim3(8, NCHUNK, BATCH), b512>>>(proj, dec, cS, cat);
    pack_bh<<<(8 * CAT_NKT * 4096) / 256, b256>>>(W_down, W_rec, nullptr, nullptr, wcat, 2, CAT_NKT);

    // cat GEMM in two M-halves: first half starts as soon as ug half 0 + scan done
    cudaStreamWaitEvent(0, evUg0, 0);
    gemm_h<0><<<dim3(8, 32), b256>>>(cat, wcat, out, CAT_NKT, H_DIM);
    cudaStreamWaitEvent(0, evUg1, 0);
    gemm_h<0><<<dim3(8, 32), b256>>>(cat + (size_t)32 * CAT_NKT * 4096, wcat,
                                     out + (size_t)32 * 128 * H_DIM, CAT_NKT, H_DIM);
}

// round 16
// speedup vs baseline: 1.5923x; 1.0593x over previous
#include <cuda_runtime.h>
#include <cuda_fp16.h>
#include <math.h>
#include <stdint.h>

#define H_DIM   1024
#define M_DIM   64
#define LS_DIM  2048
#define BATCH   4
#define SEQ     2048
#define NTOK    8192
#define PROJ_W  384
#define CHUNK   64
#define NCHUNK  32
#define CAT_NKT 66            // 64 ktiles of t (k=2048) + 2 ktiles of sr (k=64)

// -------- scratch (device globals; allocation-free rule) --------------------
__device__ __half g_xh[(size_t)NTOK * H_DIM];               // x, A-frag tiles [mt][kt][4096h]
__device__ __half g_projh[(size_t)NTOK * PROJ_W];           // natural row-major fp16
__device__ float  g_decay[NTOK];
__device__ __half g_cat[(size_t)64 * CAT_NKT * 4096];       // [t|sr] A-frag tiles
__device__ __half g_wp[(size_t)3 * 32 * 4096];              // B-frag tiles: [Wk|Wv|Wql|Wqr]
__device__ __half g_wug[(size_t)32 * 32 * 4096];            // B-frag tiles: [u64|g64] x32
__device__ __half g_wcat[(size_t)8 * CAT_NKT * 4096];       // B-frag tiles: [Wdown;Wrec]
__device__ float  g_cA[BATCH * NCHUNK];
__device__ float  g_cB[(size_t)BATCH * NCHUNK * 4096];
__device__ float  g_cS[(size_t)BATCH * NCHUNK * 4096];

// ---------------------------------------------------------------------------
__device__ __forceinline__ float silu_f(float x) { return x / (1.0f + expf(-x)); }

__device__ __forceinline__ void mma_h(float* c, uint4 a, uint32_t b0, uint32_t b1) {
    asm volatile(
        "mma.sync.aligned.m16n8k16.row.col.f32.f16.f16.f32 "
        "{%0,%1,%2,%3}, {%4,%5,%6,%7}, {%8,%9}, {%0,%1,%2,%3};"
        : "+f"(c[0]), "+f"(c[1]), "+f"(c[2]), "+f"(c[3])
        : "r"(a.x), "r"(a.y), "r"(a.z), "r"(a.w), "r"(b0), "r"(b1));
}

#define CP16(s, g)  asm volatile("cp.async.cg.shared.global [%0], [%1], 16;" :: "r"(s), "l"(g))
#define CPCOMMITG() asm volatile("cp.async.commit_group;" ::: "memory")
#define CPWAIT1()   asm volatile("cp.async.wait_group 1;" ::: "memory")

// A-frag-major half offset within a 128(m) x 32(k) tile (4096 halfs).
__device__ __forceinline__ int ah_off(int m, int k) {
    int wr = m >> 5, mi = (m >> 4) & 1, h = (m >> 3) & 1, g = m & 7;
    int ks = k >> 4, u = (k >> 3) & 1, tg = (k >> 1) & 3, e = k & 1;
    int word = ((wr * 4 + ks * 2 + mi) * 32 + g * 4 + tg) * 4 + h + 2 * u;
    return word * 2 + e;
}

// ---------------------------------------------------------------------------
// fp16 tensor-core GEMM (round-13 proven config). 256 threads = 8 warps (4x2),
// warp tile 32x64, BM=BN=128. Stage = 64 k -> one barrier per 64 k.
// A: direct LDG.128, register double-buffered per 32-k half.
// B: 3-stage cp.async STATIC smem ring (16KB/stage, 48KB).
// WB 0: natural fp32 store (ldc). WB 1: fused swiglu -> g_cat (STG.128).
// WB 2: natural fp16 store (ldc in halfs).
// nkt must be even.
// ---------------------------------------------------------------------------
template <int WB>
__global__ __launch_bounds__(256, 2) void gemm_h(
    const __half* __restrict__ A, const __half* __restrict__ B, void* __restrict__ Cv,
    int nkt, int ldc)
{
    __shared__ uint32_t sm[12288];    // 3 stages x 4096 words (16KB) ; swiglu reuse

    const int tid = threadIdx.x;
    const int w = tid >> 5, lane = tid & 31;
    const int wr = w & 3, wc = w >> 2;
    const int g = lane >> 2, tg = lane & 3;
    const int nst = nkt >> 1;

    const uint4* At = (const uint4*)(A + (size_t)blockIdx.y * nkt * 4096) + (wr * 4) * 32 + lane;
    const __half* Bbase = B + (size_t)blockIdx.x * nkt * 4096 + tid * 32;
    const uint32_t sb = (uint32_t)__cvta_generic_to_shared(sm);

    float acc[2][8][4];
#pragma unroll
    for (int mi = 0; mi < 2; ++mi)
#pragma unroll
        for (int j = 0; j < 8; ++j)
#pragma unroll
            for (int q = 0; q < 4; ++q) acc[mi][j][q] = 0.0f;

    // prologue: B stages 0,1 ; A frags ktile 0
#pragma unroll
    for (int p = 0; p < 2; ++p) {
        uint32_t sa = sb + p * 16384u + tid * 64u;
        const __half* gb = Bbase + (size_t)p * 8192;
        CP16(sa, gb); CP16(sa + 16, gb + 8); CP16(sa + 32, gb + 16); CP16(sa + 48, gb + 24);
        CPCOMMITG();
    }
    uint4 Ac[4], An[4];
#pragma unroll
    for (int q = 0; q < 4; ++q) Ac[q] = At[q * 32];

    for (int st = 0; st < nst; ++st) {
        const int s = st - (st / 3) * 3;
        CPWAIT1();
        __syncthreads();
        if (st + 2 < nst) {
            const int s2 = (st + 2) - ((st + 2) / 3) * 3;
            uint32_t sa = sb + s2 * 16384u + tid * 64u;
            const __half* gb = Bbase + (size_t)(st + 2) * 8192;
            CP16(sa, gb); CP16(sa + 16, gb + 8); CP16(sa + 32, gb + 16); CP16(sa + 48, gb + 24);
        }
        CPCOMMITG();

#pragma unroll
        for (int half = 0; half < 2; ++half) {
            const int kt = st * 2 + half;
            if (kt + 1 < nkt) {
                const uint4* An_p = At + (size_t)(kt + 1) * 512;
#pragma unroll
                for (int q = 0; q < 4; ++q) An[q] = An_p[q * 32];
            }
            const uint32_t* bs = sm + s * 4096 + half * 2048;
#pragma unroll
            for (int ks = 0; ks < 2; ++ks) {
#pragma unroll
                for (int jp = 0; jp < 4; ++jp) {
                    uint4 bf = *(const uint4*)(bs + ((ks * 2 + wc) * 4 + jp) * 128 + lane * 4);
                    mma_h(acc[0][jp * 2],     Ac[ks * 2 + 0], bf.x, bf.y);
                    mma_h(acc[1][jp * 2],     Ac[ks * 2 + 1], bf.x, bf.y);
                    mma_h(acc[0][jp * 2 + 1], Ac[ks * 2 + 0], bf.z, bf.w);
                    mma_h(acc[1][jp * 2 + 1], Ac[ks * 2 + 1], bf.z, bf.w);
                }
            }
#pragma unroll
            for (int q = 0; q < 4; ++q) Ac[q] = An[q];
        }
    }

    if (WB == 0) {
        float* C = (float*)Cv;
#pragma unroll
        for (int mi = 0; mi < 2; ++mi) {
            const int row0 = blockIdx.y * 128 + wr * 32 + mi * 16 + g;
#pragma unroll
            for (int j = 0; j < 8; ++j) {
                const int col = blockIdx.x * 128 + wc * 64 + j * 8 + tg * 2;
                float* p0 = C + (size_t)row0 * ldc + col;
                float* p1 = p0 + 8 * ldc;
                p0[0] = acc[mi][j][0]; p0[1] = acc[mi][j][1];
                p1[0] = acc[mi][j][2]; p1[1] = acc[mi][j][3];
            }
        }
    } else if (WB == 2) {
        __half* C = (__half*)Cv;
#pragma unroll
        for (int mi = 0; mi < 2; ++mi) {
            const int row0 = blockIdx.y * 128 + wr * 32 + mi * 16 + g;
#pragma unroll
            for (int j = 0; j < 8; ++j) {
                const int col = blockIdx.x * 128 + wc * 64 + j * 8 + tg * 2;
                __half2 v0 = __floats2half2_rn(acc[mi][j][0], acc[mi][j][1]);
                __half2 v1 = __floats2half2_rn(acc[mi][j][2], acc[mi][j][3]);
                *(__half2*)(C + (size_t)row0 * ldc + col) = v0;
                *(__half2*)(C + (size_t)(row0 + 8) * ldc + col) = v1;
            }
        }
    } else {
        // fused swiglu: wc==1 warps hold gate; exchange silu(gate) via smem;
        // wc==0 warps store paired-j uint4 (coalesced STG.128)
        __syncthreads();
        float* smf = (float*)sm;               // [c][r], stride 129 (8256 <= 12288)
        if (wc == 1) {
#pragma unroll
            for (int mi = 0; mi < 2; ++mi) {
                const int r = wr * 32 + mi * 16 + g;
#pragma unroll
                for (int j = 0; j < 8; ++j) {
                    const int c = j * 8 + tg * 2;
                    smf[c * 129 + r]           = silu_f(acc[mi][j][0]);
                    smf[(c + 1) * 129 + r]     = silu_f(acc[mi][j][1]);
                    smf[c * 129 + r + 8]       = silu_f(acc[mi][j][2]);
                    smf[(c + 1) * 129 + r + 8] = silu_f(acc[mi][j][3]);
                }
            }
        }
        __syncthreads();
        if (wc == 0) {
            __half* Ch = (__half*)Cv;
            const size_t mtb = (size_t)blockIdx.y * CAT_NKT * 4096;
#pragma unroll
            for (int mi = 0; mi < 2; ++mi) {
                const int r = wr * 32 + mi * 16 + g;
#pragma unroll
                for (int jq = 0; jq < 4; ++jq) {
                    const int j0 = jq * 2, j1 = jq * 2 + 1;
                    const int c = j0 * 8 + tg * 2;
                    float t0 = acc[mi][j0][0] * smf[c * 129 + r];
                    float t1 = acc[mi][j0][1] * smf[(c + 1) * 129 + r];
                    float t2 = acc[mi][j0][2] * smf[c * 129 + r + 8];
                    float t3 = acc[mi][j0][3] * smf[(c + 1) * 129 + r + 8];
                    float s0 = acc[mi][j1][0] * smf[(c + 8) * 129 + r];
                    float s1 = acc[mi][j1][1] * smf[(c + 9) * 129 + r];
                    float s2 = acc[mi][j1][2] * smf[(c + 8) * 129 + r + 8];
                    float s3 = acc[mi][j1][3] * smf[(c + 9) * 129 + r + 8];
                    const int colg = blockIdx.x * 64 + c;
                    const int kt = colg >> 5, kk = colg & 31;
                    __half* tb = Ch + mtb + (size_t)kt * 4096;
                    __half2 v0 = __floats2half2_rn(t0, t1);
                    __half2 v1 = __floats2half2_rn(t2, t3);
                    __half2 v2 = __floats2half2_rn(s0, s1);
                    __half2 v3 = __floats2half2_rn(s2, s3);
                    uint4 pk;
                    pk.x = *(uint32_t*)&v0; pk.y = *(uint32_t*)&v1;
                    pk.z = *(uint32_t*)&v2; pk.w = *(uint32_t*)&v3;
                    *(uint4*)(tb + ah_off(r, kk)) = pk;
                }
            }
        }
    }
}

// ---------------------------------------------------------------------------
// Packers (gather by output half index)
// ---------------------------------------------------------------------------
__global__ __launch_bounds__(256) void pack_xh(const float* __restrict__ x, __half* __restrict__ out)
{
    int o = blockIdx.x * 256 + threadIdx.x;       // NTOK * H halfs
    int tile = o >> 12, hi = o & 4095;
    int wd = hi >> 1, e = hi & 1;
    int idx = wd >> 7, lane = (wd >> 2) & 31, reg = wd & 3;
    int g = lane >> 2, tg = lane & 3;
    int wr = idx >> 2, ks = (idx >> 1) & 1, mi = idx & 1, h = reg & 1, u = reg >> 1;
    int m = wr * 32 + mi * 16 + h * 8 + g;
    int k = ks * 16 + u * 8 + tg * 2 + e;
    int mt = tile >> 5, kt = tile & 31;
    out[o] = __float2half_rn(x[(size_t)(mt * 128 + m) * H_DIM + kt * 32 + k]);
}

// B-frag packer. mode 0: wp (nkt=32), 1: wug (nkt=32), 2: wcat (nkt=66)
__global__ __launch_bounds__(256) void pack_bh(
    const float* __restrict__ S0, const float* __restrict__ S1,
    const float* __restrict__ S2, const float* __restrict__ S3,
    __half* __restrict__ out, int mode, int nkt)
{
    int o = blockIdx.x * 256 + threadIdx.x;
    int tile = o >> 12, hi = o & 4095;
    int nt = tile / nkt, kt = tile - nt * nkt;
    int wd = hi >> 1, e = hi & 1;
    int idx = wd >> 7, lane = (wd >> 2) & 31, wreg = wd & 3;
    int g = lane >> 2, tg = lane & 3;
    int jp = idx & 3, t2 = idx >> 2;
    int ks = t2 >> 1, wc = t2 & 1;
    int j = jp * 2 + (wreg >> 1), r = wreg & 1;
    int nl = wc * 64 + j * 8 + g;
    int kg = kt * 32 + ks * 16 + r * 8 + tg * 2 + e;

    float v;
    if (mode == 0) {
        int n = nt * 128 + nl;
        if (n < 128)      v = S0[(size_t)kg * 128 + n];
        else if (n < 256) v = S1[(size_t)kg * 128 + (n - 128)];
        else if (n < 320) v = S2[(size_t)kg * 64 + (n - 256)];
        else              v = S3[(size_t)kg * 64 + (n - 320)];
    } else if (mode == 1) {
        int col = nt * 64 + (nl & 63);
        v = (nl < 64) ? S0[(size_t)kg * LS_DIM + col] : S1[(size_t)kg * LS_DIM + col];
    } else {
        int n = nt * 128 + nl;
        v = (kg < 2048) ? S0[(size_t)kg * H_DIM + n] : S1[(size_t)(kg - 2048) * H_DIM + n];
    }
    out[o] = __float2half_rn(v);
}

// ---------------------------------------------------------------------------
__global__ __launch_bounds__(256) void decay_kernel(
    const float* __restrict__ x, const float* __restrict__ Wd, float* __restrict__ dec)
{
    const int token = blockIdx.x * 8 + (threadIdx.x >> 5);
    const int lane = threadIdx.x & 31;
    const float* xr = x + (size_t)token * H_DIM;
    float s = 0.0f;
#pragma unroll 8
    for (int j = lane; j < H_DIM; j += 32) s = fmaf(xr[j], Wd[j], s);
#pragma unroll
    for (int o = 16; o; o >>= 1) s += __shfl_xor_sync(0xffffffffu, s, o);
    if (lane == 0) dec[token] = 1.0f / (1.0f + expf(-s));
}

// ---------------------------------------------------------------------------
// Chunked scan — fp32 state, fp16 proj inputs (pass2 fully parallel)
// ---------------------------------------------------------------------------
__global__ __launch_bounds__(512) void scan_pass1(
    const __half* __restrict__ proj, const float* __restrict__ decay,
    float* __restrict__ cA, float* __restrict__ cB)
{
    const int b = blockIdx.y, c = blockIdx.x;
    const int tid = threadIdx.x;
    const int m = tid & 63, n0 = (tid >> 6) * 8;
    const size_t base = (size_t)b * SEQ + c * CHUNK;

    float st[8];
#pragma unroll
    for (int j = 0; j < 8; ++j) st[j] = 0.0f;
    float a = 1.0f;

    for (int s = 0; s < CHUNK; ++s) {
        const __half* row = proj + (base + s) * PROJ_W;
        float d = decay[base + s];
        float k0 = __half2float(row[m]), k1 = __half2float(row[64 + m]);
        uint4 u0 = *(const uint4*)(row + 128 + n0);
        uint4 u1 = *(const uint4*)(row + 192 + n0);
        const __half2* h0 = (const __half2*)&u0;
        const __half2* h1 = (const __half2*)&u1;
        float v0[8], v1[8];
#pragma unroll
        for (int q = 0; q < 4; ++q) {
            float2 f0 = __half22float2(h0[q]);
            float2 f1 = __half22float2(h1[q]);
            v0[q * 2] = f0.x; v0[q * 2 + 1] = f0.y;
            v1[q * 2] = f1.x; v1[q * 2 + 1] = f1.y;
        }
        a *= d;
        float omd = 1.0f - d;
#pragma unroll
        for (int j = 0; j < 8; ++j) {
            float wv = 0.5f * (k0 * v0[j] + k1 * v1[j]);
            st[j] = fmaf(d, st[j], omd * wv);
        }
    }
    float* o = cB + ((size_t)(b * NCHUNK + c) * 64 + m) * 64 + n0;
#pragma unroll
    for (int j = 0; j < 8; ++j) o[j] = st[j];
    if (tid == 0) cA[b * NCHUNK + c] = a;
}

// grid (NCHUNK, BATCH), 512 threads — parallel backward weighted sum
__global__ __launch_bounds__(512) void scan_pass2(
    const float* __restrict__ init_state, const float* __restrict__ cA,
    const float* __restrict__ cB, float* __restrict__ cS)
{
    const int c = blockIdx.x, b = blockIdx.y;
    const int i0 = threadIdx.x * 8;
    __shared__ float sa[NCHUNK];
    if ((int)threadIdx.x < c) sa[threadIdx.x] = cA[b * NCHUNK + threadIdx.x];
    __syncthreads();

    float st[8];
#pragma unroll
    for (int j = 0; j < 8; ++j) st[j] = 0.0f;
    float w = 1.0f;

    for (int j = c - 1; j >= 0; --j) {
        const float* Bp = cB + (size_t)(b * NCHUNK + j) * 4096 + i0;
        float4 b0 = *(const float4*)Bp;
        float4 b1 = *(const float4*)(Bp + 4);
        st[0] = fmaf(w, b0.x, st[0]); st[1] = fmaf(w, b0.y, st[1]);
        st[2] = fmaf(w, b0.z, st[2]); st[3] = fmaf(w, b0.w, st[3]);
        st[4] = fmaf(w, b1.x, st[4]); st[5] = fmaf(w, b1.y, st[5]);
        st[6] = fmaf(w, b1.z, st[6]); st[7] = fmaf(w, b1.w, st[7]);
        w *= sa[j];
    }
    const float* ip = init_state + i0;
    float* o = cS + (size_t)(b * NCHUNK + c) * 4096 + i0;
#pragma unroll
    for (int j = 0; j < 8; ++j) o[j] = fmaf(w, ip[j], st[j]);
}

// Barrier-free pass3: 512 threads = 16 n-groups x 32 lanes; each lane carries
// states (m=lane, m=lane+32); 64-way m-reduction = local add + 5 shuffles.
// grid (4, NCHUNK, BATCH).
__global__ __launch_bounds__(512) void scan_pass3(
    const __half* __restrict__ proj, const float* __restrict__ decay,
    const float* __restrict__ cS, __half* __restrict__ cat)
{
    const int b = blockIdx.z, c = blockIdx.y;
    const int n0 = blockIdx.x * 16;
    const int tid = threadIdx.x;
    const int nl = tid >> 5;          // 0..15
    const int lane = tid & 31;
    const int n = n0 + nl;
    const int m0 = lane, m1 = lane + 32;

    const size_t sbase = (size_t)(b * NCHUNK + c) * 4096;
    float st0 = cS[sbase + m0 * 64 + n];
    float st1 = cS[sbase + m1 * 64 + n];
    const size_t base = (size_t)b * SEQ + c * CHUNK;

    const __half* row = proj + base * PROJ_W;
    float d = decay[base];
    float k00 = __half2float(row[m0]),      k10 = __half2float(row[64 + m0]);
    float k01 = __half2float(row[m1]),      k11 = __half2float(row[64 + m1]);
    float v0  = __half2float(row[128 + n]), v1  = __half2float(row[192 + n]);
    float ql0 = __half2float(row[256 + m0]), ql1 = __half2float(row[256 + m1]);
    float qrn = __half2float(row[320 + n]);

    for (int s = 0; s < CHUNK; ++s) {
        float nd = 0.f, nk00 = 0.f, nk10 = 0.f, nk01 = 0.f, nk11 = 0.f;
        float nv0 = 0.f, nv1 = 0.f, nql0 = 0.f, nql1 = 0.f, nqr = 0.f;
        if (s + 1 < CHUNK) {
            const __half* nr = proj + (base + s + 1) * PROJ_W;
            nd = decay[base + s + 1];
            nk00 = __half2float(nr[m0]);      nk10 = __half2float(nr[64 + m0]);
            nk01 = __half2float(nr[m1]);      nk11 = __half2float(nr[64 + m1]);
            nv0  = __half2float(nr[128 + n]); nv1  = __half2float(nr[192 + n]);
            nql0 = __half2float(nr[256 + m0]); nql1 = __half2float(nr[256 + m1]);
            nqr  = __half2float(nr[320 + n]);
        }
        float omd = 1.0f - d;
        st0 = fmaf(d, st0, omd * (0.5f * (k00 * v0 + k10 * v1)));
        st1 = fmaf(d, st1, omd * (0.5f * (k01 * v0 + k11 * v1)));

        float p = ql0 * st0 + ql1 * st1;
#pragma unroll
        for (int o = 16; o; o >>= 1) p += __shfl_xor_sync(0xffffffffu, p, o);
        if (lane == 0) {
            float rd = p * qrn;
            int token = (int)(base + s);
            int mt = token >> 7, r = token & 127;
            int kt = 64 + (n >> 5), kk = n & 31;
            cat[((size_t)mt * CAT_NKT + kt) * 4096 + ah_off(r, kk)] = __float2half_rn(silu_f(rd));
        }
        d = nd; k00 = nk00; k10 = nk10; k01 = nk01; k11 = nk11;
        v0 = nv0; v1 = nv1; ql0 = nql0; ql1 = nql1; qrn = nqr;
    }
}

// ---------------------------------------------------------------------------
extern "C" void kernel_launch(void* const* d_in, const int* in_sizes, int n_in,
                              void* d_out, int out_size)
{
    const float* x       = (const float*)d_in[0];
    const float* W_decay = (const float*)d_in[1];
    const float* W_key   = (const float*)d_in[2];
    const float* W_value = (const float*)d_in[3];
    const float* W_ql    = (const float*)d_in[4];
    const float* W_qr    = (const float*)d_in[5];
    const float* W_rec   = (const float*)d_in[6];
    const float* W_up    = (const float*)d_in[7];
    const float* W_gate  = (const float*)d_in[8];
    const float* W_down  = (const float*)d_in[9];
    const float* init_st = (const float*)d_in[10];
    float* out = (float*)d_out;

    void *p_xh, *p_proj, *p_dec, *p_cat, *p_wp, *p_wug, *p_wcat, *p_cA, *p_cB, *p_cS;
    cudaGetSymbolAddress(&p_xh,   g_xh);
    cudaGetSymbolAddress(&p_proj, g_projh);
    cudaGetSymbolAddress(&p_dec,  g_decay);
    cudaGetSymbolAddress(&p_cat,  g_cat);
    cudaGetSymbolAddress(&p_wp,   g_wp);
    cudaGetSymbolAddress(&p_wug,  g_wug);
    cudaGetSymbolAddress(&p_wcat, g_wcat);
    cudaGetSymbolAddress(&p_cA,   g_cA);
    cudaGetSymbolAddress(&p_cB,   g_cB);
    cudaGetSymbolAddress(&p_cS,   g_cS);
    __half* xh   = (__half*)p_xh;
    __half* proj = (__half*)p_proj;
    float*  dec  = (float*)p_dec;
    __half* cat  = (__half*)p_cat;
    __half* wp   = (__half*)p_wp;
    __half* wug  = (__half*)p_wug;
    __half* wcat = (__half*)p_wcat;
    float*  cA   = (float*)p_cA;
    float*  cB   = (float*)p_cB;
    float*  cS   = (float*)p_cS;

    // one-time stream/event setup (no device memory involved)
    static cudaStream_t s_aux = nullptr;
    static cudaEvent_t evFork = nullptr, evXh = nullptr, evUg0 = nullptr, evUg1 = nullptr;
    if (!s_aux) {
        int prLo = 0, prHi = 0;
        cudaDeviceGetStreamPriorityRange(&prLo, &prHi);
        cudaStreamCreateWithPriority(&s_aux, cudaStreamNonBlocking, prHi);  // high priority
        cudaEventCreateWithFlags(&evFork, cudaEventDisableTiming);
        cudaEventCreateWithFlags(&evXh, cudaEventDisableTiming);
        cudaEventCreateWithFlags(&evUg0, cudaEventDisableTiming);
        cudaEventCreateWithFlags(&evUg1, cudaEventDisableTiming);
    }

    const dim3 b256(256), b512(512);

    // fork immediately: aux runs the wug pack (independent of x)
    cudaEventRecord(evFork, 0);
    cudaStreamWaitEvent(s_aux, evFork, 0);
    pack_bh<<<(32 * 32 * 4096) / 256, b256, 0, s_aux>>>(W_up, W_gate, nullptr, nullptr, wug, 1, 32);

    // main stream: pack x
    pack_xh<<<(NTOK * H_DIM) / 256, b256>>>(x, xh);
    cudaEventRecord(evXh, 0);

    // aux: ug GEMM in two M-halves (fused swiglu -> cat kt 0..63)
    cudaStreamWaitEvent(s_aux, evXh, 0);
    gemm_h<1><<<dim3(32, 32), b256, 0, s_aux>>>(xh, wug, cat, 32, 0);
    cudaEventRecord(evUg0, s_aux);
    gemm_h<1><<<dim3(32, 32), b256, 0, s_aux>>>(xh + (size_t)32 * 32 * 4096, wug,
                                                cat + (size_t)32 * CAT_NKT * 4096, 32, 0);
    cudaEventRecord(evUg1, s_aux);

    // main stream: proj chain + scan (all batches)
    pack_bh<<<(3 * 32 * 4096) / 256, b256>>>(W_key, W_value, W_ql, W_qr, wp, 0, 32);
    decay_kernel<<<NTOK / 8, b256>>>(x, W_decay, dec);
    gemm_h<2><<<dim3(3, 64), b256>>>(xh, wp, proj, 32, PROJ_W);
    scan_pass1<<<dim3(NCHUNK, BATCH), b512>>>(proj, dec, cA, cB);
    scan_pass2<<<dim3(NCHUNK, BATCH), b512>>>(init_st, cA, cB, cS);
    scan_pass3<<<dim3(4, NCHUNK, BATCH), b512>>>(proj, dec, cS, cat);
    pack_bh<<<(8 * CAT_NKT * 4096) / 256, b256>>>(W_down, W_rec, nullptr, nullptr, wcat, 2, CAT_NKT);

    // cat GEMM in two M-halves: first half starts as soon as ug half 0 + scan done
    cudaStreamWaitEvent(0, evUg0, 0);
    gemm_h<0><<<dim3(8, 32), b256>>>(cat, wcat, out, CAT_NKT, H_DIM);
    cudaStreamWaitEvent(0, evUg1, 0);
    gemm_h<0><<<dim3(8, 32), b256>>>(cat + (size_t)32 * CAT_NKT * 4096, wcat,
                                     out + (size_t)32 * 128 * H_DIM, CAT_NKT, H_DIM);
}